// round 5
// baseline (speedup 1.0000x reference)
#include <cuda_runtime.h>
#include <stdint.h>

// out[i] = -cost[i, inputs[i]] * mask[i]
// cost: float32 [N, V], inputs: int32 [N], mask: float32 [N], out: float32 [N]
// N = 16384, V = 32000.
//
// One graph node; harness replay overhead (~5us) dominates, kernel ~1.5us.
// This version targets the kernel's two-DRAM-round-trip chain:
//  - int4/float4 loads: 4 rows per thread, one coalesced transaction each
//  - 4 independent gathers per thread (MLP=4) -> TLB PTW fully overlapped
//    (cost spans 1024 2MB pages > 128-entry TLB; PTW hidden only at MLP>=4)
//  - float4 store
// Grid 128 x 32: one warp per CTA, spread across ~128 SMs' L1tex queues.

__global__ void masked_nll_v4(const float* __restrict__ cost,
                              const int4* __restrict__ idx4,
                              const float4* __restrict__ mask4,
                              float4* __restrict__ out4,
                              int n4, unsigned v) {
    unsigned t = blockIdx.x * blockDim.x + threadIdx.x;
    if (t >= (unsigned)n4) return;

    int4   idx = idx4[t];     // indices for rows 4t .. 4t+3
    float4 m   = mask4[t];    // independent of idx load -> overlapped

    unsigned base = 4u * t * v;   // max 16384*32000 < 2^31, exact in 32 bits
    // 4 independent scattered gathers (MLP=4)
    float p0 = __ldg(cost + (base          + (unsigned)idx.x));
    float p1 = __ldg(cost + (base +     v  + (unsigned)idx.y));
    float p2 = __ldg(cost + (base + 2u * v + (unsigned)idx.z));
    float p3 = __ldg(cost + (base + 3u * v + (unsigned)idx.w));

    float4 r;
    r.x = -p0 * m.x;
    r.y = -p1 * m.y;
    r.z = -p2 * m.z;
    r.w = -p3 * m.w;
    out4[t] = r;
}

// Scalar tail fallback (not used for N=16384, kept for generality).
__global__ void masked_nll_tail(const float* __restrict__ cost,
                                const int* __restrict__ idx,
                                const float* __restrict__ mask,
                                float* __restrict__ out,
                                int start, int n, unsigned v) {
    int i = start + blockIdx.x * blockDim.x + threadIdx.x;
    if (i >= n) return;
    out[i] = -__ldg(cost + (unsigned)i * v + (unsigned)idx[i]) * mask[i];
}

extern "C" void kernel_launch(void* const* d_in, const int* in_sizes, int n_in,
                              void* d_out, int out_size) {
    const float* cost = (const float*)d_in[0];
    const int*   idx  = (const int*)d_in[1];
    const float* mask = (const float*)d_in[2];
    float*       out  = (float*)d_out;

    int n = in_sizes[1];
    unsigned v = (unsigned)(in_sizes[0] / n);

    int n4 = n / 4;                      // 4096 for N=16384
    int threads = 32;
    int blocks = (n4 + threads - 1) / threads;   // 128 CTAs
    masked_nll_v4<<<blocks, threads>>>(cost, (const int4*)idx,
                                       (const float4*)mask, (float4*)out,
                                       n4, v);
    int rem = n - n4 * 4;
    if (rem > 0) {
        masked_nll_tail<<<1, 128>>>(cost, idx, mask, out, n4 * 4, n, v);
    }
}

// round 6
// speedup vs baseline: 1.0048x; 1.0048x over previous
#include <cuda_runtime.h>
#include <stdint.h>

// out[i] = -cost[i, inputs[i]] * mask[i]
// cost: float32 [N, V], inputs: int32 [N], mask: float32 [N], out: float32 [N]
// N = 16384, V = 32000.
//
// Regime note: during timed graph replays the whole working set is L2-hot
// (idx/mask/out = 64KB each; the gathers hit the same ~2MB of cost lines each
// replay; L2 = 126MB). The kernel is ~1.5us of a ~6.5us total; the rest is
// per-node graph replay overhead. This version: 2 rows/thread (int2/float2),
// 8192 threads = 64 CTAs x 128 -> one wave, 2 independent gathers per thread,
// per-warp outstanding gathers (64) near but not far over the ~55 LDG cap.

__global__ void masked_nll_v2(const float* __restrict__ cost,
                              const int2* __restrict__ idx2,
                              const float2* __restrict__ mask2,
                              float2* __restrict__ out2,
                              int n2, unsigned v) {
    unsigned t = blockIdx.x * blockDim.x + threadIdx.x;
    if (t >= (unsigned)n2) return;

    int2   idx = idx2[t];    // indices for rows 2t, 2t+1
    float2 m   = mask2[t];   // independent load, overlapped

    unsigned base = 2u * t * v;          // < 2^31, exact
    float p0 = __ldg(cost + (base     + (unsigned)idx.x));
    float p1 = __ldg(cost + (base + v + (unsigned)idx.y));

    float2 r;
    r.x = -p0 * m.x;
    r.y = -p1 * m.y;
    out2[t] = r;
}

// Scalar tail (unused for N=16384; kept for generality).
__global__ void masked_nll_tail(const float* __restrict__ cost,
                                const int* __restrict__ idx,
                                const float* __restrict__ mask,
                                float* __restrict__ out,
                                int start, int n, unsigned v) {
    int i = start + blockIdx.x * blockDim.x + threadIdx.x;
    if (i >= n) return;
    out[i] = -__ldg(cost + (unsigned)i * v + (unsigned)idx[i]) * mask[i];
}

extern "C" void kernel_launch(void* const* d_in, const int* in_sizes, int n_in,
                              void* d_out, int out_size) {
    const float* cost = (const float*)d_in[0];
    const int*   idx  = (const int*)d_in[1];
    const float* mask = (const float*)d_in[2];
    float*       out  = (float*)d_out;

    int n = in_sizes[1];
    unsigned v = (unsigned)(in_sizes[0] / n);

    int n2 = n / 2;                          // 8192
    int threads = 128;
    int blocks = (n2 + threads - 1) / threads;   // 64 CTAs
    masked_nll_v2<<<blocks, threads>>>(cost, (const int2*)idx,
                                       (const float2*)mask, (float2*)out,
                                       n2, v);
    int rem = n - n2 * 2;
    if (rem > 0) {
        masked_nll_tail<<<1, 64>>>(cost, idx, mask, out, n2 * 2, n, v);
    }
}

// round 7
// speedup vs baseline: 1.4150x; 1.4082x over previous
#include <cuda_runtime.h>
#include <stdint.h>

// out[i] = -cost[i, inputs[i]] * mask[i]
// cost: float32 [N, V], inputs: int32 [N], mask: float32 [N], out: float32 [N]
// N = 16384, V = 32000.
//
// Converged configuration. Measured facts across rounds:
//   - one graph node costs ~5us replay overhead (2 nodes: 12.8us, 1 node: 6.6us)
//   - scalar / x2 / x4 vectorization all tie within one 0.128us timer tick
//     (working set is L2-hot during replays; gather latency ~250cyc, hidden)
//   - best measured: scalar, 128 threads x 128 CTAs (6.528us)
// This version = that config, minus the per-thread bounds check (N is an
// exact multiple of 128; a guarded kernel remains as the generic fallback).

__global__ void __launch_bounds__(128, 1)
masked_nll_exact(const float* __restrict__ cost,
                 const int* __restrict__ idx,
                 const float* __restrict__ mask,
                 float* __restrict__ out,
                 unsigned v) {
    unsigned i = blockIdx.x * 128u + threadIdx.x;
    // Element offset fits in 32 bits: 16384*32000 + 31999 < 2^31.
    unsigned off = i * v + (unsigned)idx[i];
    out[i] = -__ldg(cost + off) * mask[i];
}

__global__ void __launch_bounds__(128, 1)
masked_nll_guarded(const float* __restrict__ cost,
                   const int* __restrict__ idx,
                   const float* __restrict__ mask,
                   float* __restrict__ out,
                   int n, unsigned v) {
    unsigned i = blockIdx.x * 128u + threadIdx.x;
    if (i >= (unsigned)n) return;
    unsigned off = i * v + (unsigned)idx[i];
    out[i] = -__ldg(cost + off) * mask[i];
}

extern "C" void kernel_launch(void* const* d_in, const int* in_sizes, int n_in,
                              void* d_out, int out_size) {
    const float* cost = (const float*)d_in[0];
    const int*   idx  = (const int*)d_in[1];
    const float* mask = (const float*)d_in[2];
    float*       out  = (float*)d_out;

    int n = in_sizes[1];                      // N = element count of inputs[]
    unsigned v = (unsigned)(in_sizes[0] / n); // V = cost elems / N

    const int threads = 128;
    if (n % threads == 0) {
        masked_nll_exact<<<n / threads, threads>>>(cost, idx, mask, out, v);
    } else {
        masked_nll_guarded<<<(n + threads - 1) / threads, threads>>>(
            cost, idx, mask, out, n, v);
    }
}